// round 1
// baseline (speedup 1.0000x reference)
#include <cuda_runtime.h>
#include <math.h>

// Problem constants
#define BB   2
#define SS   1024
#define DD   1024
#define HH   16
#define DKK  64
#define FF   4096
#define LL   4
#define VV   32000
#define MM   (BB*SS)        // 2048 tokens
#define LNEPS 1e-5f

// ---------------- scratch (device globals; no allocation allowed) ----------
__device__ float g_x [MM*DD];                    // residual stream
__device__ float g_q [MM*DD];
__device__ float g_k [MM*DD];
__device__ float g_v [MM*DD];
__device__ float g_o [MM*DD];
__device__ float g_ff[MM*FF];                    // FFN hidden
__device__ float g_sc[(size_t)BB*HH*SS*SS];      // attention scores (134 MB)

// ---------------- embedding + sinusoidal PE --------------------------------
__global__ void embed_pe_kernel(const int* __restrict__ ids,
                                const float* __restrict__ emb,
                                float* __restrict__ x)
{
    int idx = blockIdx.x * 256 + threadIdx.x;    // over MM*DD
    int m = idx >> 10;            // token index (D=1024)
    int d = idx & 1023;
    int s = m & (SS - 1);         // position within sequence
    int tok = ids[m];
    int twohalf = (d >> 1) << 1;  // 2*(d//2)
    // div = exp(-2*(d//2) * ln(10000)/D)
    float div = __expf(-(float)twohalf * (9.210340371976184f / (float)DD));
    float ang = (float)s * div;
    float pe  = (d & 1) ? cosf(ang) : sinf(ang);
    x[idx] = emb[(size_t)tok * DD + d] * 32.0f + pe;   // sqrt(1024)=32
}

// ---------------- generic NT SGEMM: C[M,N] = A[M,K] @ B[N,K]^T (+bias, relu)
// 128x128 tile, BK=8, 256 threads, 8x8 microtile. All dims divisible.
__global__ __launch_bounds__(256)
void sgemm_nt(const float* __restrict__ A, const float* __restrict__ Bw,
              const float* __restrict__ bias, float* __restrict__ C,
              int M, int N, int K, int relu)
{
    __shared__ float As[8][128];
    __shared__ float Bs[8][128];
    int tid = threadIdx.x;
    int m0 = blockIdx.y * 128, n0 = blockIdx.x * 128;
    int lrow = tid >> 1;              // 0..127
    int lcol = (tid & 1) << 2;        // 0 or 4
    const float* Ap = A  + (size_t)(m0 + lrow) * K + lcol;
    const float* Bp = Bw + (size_t)(n0 + lrow) * K + lcol;
    int ty = tid >> 4, tx = tid & 15;

    float acc[8][8];
#pragma unroll
    for (int i = 0; i < 8; i++)
#pragma unroll
        for (int j = 0; j < 8; j++) acc[i][j] = 0.f;

    for (int k0 = 0; k0 < K; k0 += 8) {
        float4 av = *(const float4*)(Ap + k0);
        float4 bv = *(const float4*)(Bp + k0);
        __syncthreads();
        As[lcol + 0][lrow] = av.x; As[lcol + 1][lrow] = av.y;
        As[lcol + 2][lrow] = av.z; As[lcol + 3][lrow] = av.w;
        Bs[lcol + 0][lrow] = bv.x; Bs[lcol + 1][lrow] = bv.y;
        Bs[lcol + 2][lrow] = bv.z; Bs[lcol + 3][lrow] = bv.w;
        __syncthreads();
#pragma unroll
        for (int kk = 0; kk < 8; kk++) {
            float a[8], b[8];
#pragma unroll
            for (int i = 0; i < 8; i++) a[i] = As[kk][ty * 8 + i];
#pragma unroll
            for (int j = 0; j < 8; j++) b[j] = Bs[kk][tx * 8 + j];
#pragma unroll
            for (int i = 0; i < 8; i++)
#pragma unroll
                for (int j = 0; j < 8; j++) acc[i][j] += a[i] * b[j];
        }
    }
#pragma unroll
    for (int i = 0; i < 8; i++) {
        int row = m0 + ty * 8 + i;
#pragma unroll
        for (int j = 0; j < 8; j++) {
            int col = n0 + tx * 8 + j;
            float v = acc[i][j];
            if (bias) v += bias[col];
            if (relu) v = fmaxf(v, 0.f);
            C[(size_t)row * N + col] = v;
        }
    }
}

// ---------------- attention scores: sc[bh,i,j] = scale * q_i . k_j, causal --
__global__ __launch_bounds__(256)
void attn_scores(const float* __restrict__ q, const float* __restrict__ kmat,
                 float* __restrict__ sc)
{
    int bh = blockIdx.z;
    int b = bh >> 4, h = bh & 15;
    int i0 = blockIdx.y * 128, j0 = blockIdx.x * 128;
    float* out = sc + (size_t)bh * SS * SS;
    int tid = threadIdx.x;

    if (j0 > i0 + 127) {   // fully masked tile
        for (int u = tid; u < 128 * 128; u += 256) {
            int i = u >> 7, j = u & 127;
            out[(size_t)(i0 + i) * SS + j0 + j] = -1e9f;
        }
        return;
    }

    const float* qb = q    + (size_t)b * SS * DD + h * DKK;
    const float* kb = kmat + (size_t)b * SS * DD + h * DKK;
    __shared__ float Qs[8][128];
    __shared__ float Ks[8][128];
    int lrow = tid >> 1, lcol = (tid & 1) << 2;
    int ty = tid >> 4, tx = tid & 15;

    float acc[8][8];
#pragma unroll
    for (int i = 0; i < 8; i++)
#pragma unroll
        for (int j = 0; j < 8; j++) acc[i][j] = 0.f;

    for (int k0 = 0; k0 < DKK; k0 += 8) {
        float4 av = *(const float4*)(qb + (size_t)(i0 + lrow) * DD + k0 + lcol);
        float4 bv = *(const float4*)(kb + (size_t)(j0 + lrow) * DD + k0 + lcol);
        __syncthreads();
        Qs[lcol + 0][lrow] = av.x; Qs[lcol + 1][lrow] = av.y;
        Qs[lcol + 2][lrow] = av.z; Qs[lcol + 3][lrow] = av.w;
        Ks[lcol + 0][lrow] = bv.x; Ks[lcol + 1][lrow] = bv.y;
        Ks[lcol + 2][lrow] = bv.z; Ks[lcol + 3][lrow] = bv.w;
        __syncthreads();
#pragma unroll
        for (int kk = 0; kk < 8; kk++) {
            float a[8], bb_[8];
#pragma unroll
            for (int i = 0; i < 8; i++) a[i]   = Qs[kk][ty * 8 + i];
#pragma unroll
            for (int j = 0; j < 8; j++) bb_[j] = Ks[kk][tx * 8 + j];
#pragma unroll
            for (int i = 0; i < 8; i++)
#pragma unroll
                for (int j = 0; j < 8; j++) acc[i][j] += a[i] * bb_[j];
        }
    }
    const float scale = 0.125f;   // 1/sqrt(64)
#pragma unroll
    for (int i = 0; i < 8; i++) {
        int row = i0 + ty * 8 + i;
#pragma unroll
        for (int j = 0; j < 8; j++) {
            int col = j0 + tx * 8 + j;
            float v = acc[i][j] * scale;
            if (col > row) v = -1e9f;
            out[(size_t)row * SS + col] = v;
        }
    }
}

// ---------------- row softmax (length 1024) ---------------------------------
__global__ __launch_bounds__(256)
void softmax_rows(float* __restrict__ sc)
{
    __shared__ float red[256];
    size_t row = blockIdx.x;
    float* p = sc + row * SS;
    int t = threadIdx.x;
    float v0 = p[t], v1 = p[t + 256], v2 = p[t + 512], v3 = p[t + 768];
    float m = fmaxf(fmaxf(v0, v1), fmaxf(v2, v3));
    red[t] = m; __syncthreads();
    for (int w = 128; w > 0; w >>= 1) {
        if (t < w) red[t] = fmaxf(red[t], red[t + w]);
        __syncthreads();
    }
    m = red[0]; __syncthreads();
    v0 = __expf(v0 - m); v1 = __expf(v1 - m);
    v2 = __expf(v2 - m); v3 = __expf(v3 - m);
    float s = v0 + v1 + v2 + v3;
    red[t] = s; __syncthreads();
    for (int w = 128; w > 0; w >>= 1) {
        if (t < w) red[t] += red[t + w];
        __syncthreads();
    }
    float inv = 1.f / red[0];
    p[t] = v0 * inv; p[t + 256] = v1 * inv;
    p[t + 512] = v2 * inv; p[t + 768] = v3 * inv;
}

// ---------------- o = attn @ v  (per head), causal K-truncated --------------
// 64x64 tile (DK=64), BK=16, 256 threads, 4x4 microtile.
__global__ __launch_bounds__(256)
void attn_av(const float* __restrict__ sc, const float* __restrict__ v,
             float* __restrict__ o)
{
    int bh = blockIdx.y;
    int b = bh >> 4, h = bh & 15;
    int i0 = blockIdx.x * 64;
    const float* A  = sc + (size_t)bh * SS * SS;
    const float* vb = v  + (size_t)b * SS * DD + h * DKK;
    __shared__ float As[16][64];
    __shared__ float Vs[16][64];
    int t  = threadIdx.x;
    int ar = t >> 2,  ac = (t & 3) << 2;    // attn tile: 64 rows x 16 k
    int vr = t >> 4,  vc = (t & 15) << 2;   // v tile:    16 k   x 64 cols
    int ty = t >> 4,  tx = t & 15;

    float acc[4][4];
#pragma unroll
    for (int i = 0; i < 4; i++)
#pragma unroll
        for (int j = 0; j < 4; j++) acc[i][j] = 0.f;

    int kmax = i0 + 64;   // attn[i,j]==0 exactly for j>i (softmax underflow)
    for (int k0 = 0; k0 < kmax; k0 += 16) {
        float4 av = *(const float4*)(A  + (size_t)(i0 + ar) * SS + k0 + ac);
        float4 vv = *(const float4*)(vb + (size_t)(k0 + vr) * DD + vc);
        __syncthreads();
        As[ac + 0][ar] = av.x; As[ac + 1][ar] = av.y;
        As[ac + 2][ar] = av.z; As[ac + 3][ar] = av.w;
        *(float4*)&Vs[vr][vc] = vv;
        __syncthreads();
#pragma unroll
        for (int kk = 0; kk < 16; kk++) {
            float a[4], bv_[4];
#pragma unroll
            for (int i = 0; i < 4; i++) a[i]   = As[kk][ty * 4 + i];
#pragma unroll
            for (int j = 0; j < 4; j++) bv_[j] = Vs[kk][tx * 4 + j];
#pragma unroll
            for (int i = 0; i < 4; i++)
#pragma unroll
                for (int j = 0; j < 4; j++) acc[i][j] += a[i] * bv_[j];
        }
    }
#pragma unroll
    for (int i = 0; i < 4; i++)
#pragma unroll
        for (int j = 0; j < 4; j++)
            o[(size_t)(b * SS + i0 + ty * 4 + i) * DD + h * DKK + tx * 4 + j]
                = acc[i][j];
}

// ---------------- out = LayerNorm(x (+ y)) * g + b --------------------------
__global__ __launch_bounds__(256)
void add_ln(const float* __restrict__ x, const float* __restrict__ y,
            const float* __restrict__ g, const float* __restrict__ bta,
            float* __restrict__ out)
{
    __shared__ float red[256];
    int row = blockIdx.x;
    int t = threadIdx.x;
    const float* xr = x + (size_t)row * DD;
    float v[4];
    float s = 0.f;
#pragma unroll
    for (int u = 0; u < 4; u++) {
        int idx = t + u * 256;
        float vv = xr[idx];
        if (y) vv += y[(size_t)row * DD + idx];
        v[u] = vv;
        s += vv;
    }
    red[t] = s; __syncthreads();
    for (int w = 128; w > 0; w >>= 1) {
        if (t < w) red[t] += red[t + w];
        __syncthreads();
    }
    float mean = red[0] * (1.f / DD); __syncthreads();
    float s2 = 0.f;
#pragma unroll
    for (int u = 0; u < 4; u++) { float d = v[u] - mean; s2 += d * d; }
    red[t] = s2; __syncthreads();
    for (int w = 128; w > 0; w >>= 1) {
        if (t < w) red[t] += red[t + w];
        __syncthreads();
    }
    float rstd = rsqrtf(red[0] * (1.f / DD) + LNEPS);
    float* orow = out + (size_t)row * DD;
#pragma unroll
    for (int u = 0; u < 4; u++) {
        int idx = t + u * 256;
        orow[idx] = (v[u] - mean) * rstd * g[idx] + bta[idx];
    }
}

// ---------------- host orchestration ---------------------------------------
extern "C" void kernel_launch(void* const* d_in, const int* in_sizes, int n_in,
                              void* d_out, int out_size)
{
    (void)in_sizes; (void)n_in; (void)out_size;
    const int*   ids    = (const int*)  d_in[0];
    const float* embedw = (const float*)d_in[1];
    const float* Wq     = (const float*)d_in[2];
    const float* bq     = (const float*)d_in[3];
    const float* Wk     = (const float*)d_in[4];
    const float* bk     = (const float*)d_in[5];
    const float* Wv     = (const float*)d_in[6];
    const float* bv     = (const float*)d_in[7];
    const float* Wo     = (const float*)d_in[8];
    const float* bo     = (const float*)d_in[9];
    const float* ln1_g  = (const float*)d_in[10];
    const float* ln1_b  = (const float*)d_in[11];
    const float* W1     = (const float*)d_in[12];
    const float* b1     = (const float*)d_in[13];
    const float* W2     = (const float*)d_in[14];
    const float* b2     = (const float*)d_in[15];
    const float* ln2_g  = (const float*)d_in[16];
    const float* ln2_b  = (const float*)d_in[17];
    const float* lnf_g  = (const float*)d_in[18];
    const float* lnf_b  = (const float*)d_in[19];
    const float* head_w = (const float*)d_in[20];
    float* out = (float*)d_out;

    float *x, *q, *k, *v, *o, *ff, *sc;
    cudaGetSymbolAddress((void**)&x,  g_x);
    cudaGetSymbolAddress((void**)&q,  g_q);
    cudaGetSymbolAddress((void**)&k,  g_k);
    cudaGetSymbolAddress((void**)&v,  g_v);
    cudaGetSymbolAddress((void**)&o,  g_o);
    cudaGetSymbolAddress((void**)&ff, g_ff);
    cudaGetSymbolAddress((void**)&sc, g_sc);

    // embedding + positional encoding
    embed_pe_kernel<<<(MM * DD) / 256, 256>>>(ids, embedw, x);

    dim3 gD (DD / 128, MM / 128);   // N=1024 GEMMs
    dim3 gF (FF / 128, MM / 128);   // N=4096 GEMM
    dim3 gV (VV / 128, MM / 128);   // head GEMM
    dim3 gSc(SS / 128, SS / 128, BB * HH);
    dim3 gAv(SS / 64, BB * HH);

    for (int l = 0; l < LL; l++) {
        const float* wq = Wq + (size_t)l * DD * DD;
        const float* wk = Wk + (size_t)l * DD * DD;
        const float* wv = Wv + (size_t)l * DD * DD;
        const float* wo = Wo + (size_t)l * DD * DD;

        sgemm_nt<<<gD, 256>>>(x, wq, bq + l * DD, q, MM, DD, DD, 0);
        sgemm_nt<<<gD, 256>>>(x, wk, bk + l * DD, k, MM, DD, DD, 0);
        sgemm_nt<<<gD, 256>>>(x, wv, bv + l * DD, v, MM, DD, DD, 0);

        attn_scores <<<gSc, 256>>>(q, k, sc);
        softmax_rows<<<BB * HH * SS, 256>>>(sc);
        attn_av     <<<gAv, 256>>>(sc, v, o);

        sgemm_nt<<<gD, 256>>>(o, wo, bo + l * DD, q, MM, DD, DD, 0); // q = o-proj
        add_ln  <<<MM, 256>>>(x, q, ln1_g + l * DD, ln1_b + l * DD, x);

        sgemm_nt<<<gF, 256>>>(x,  W1 + (size_t)l * FF * DD, b1 + l * FF, ff,
                              MM, FF, DD, 1);
        sgemm_nt<<<gD, 256>>>(ff, W2 + (size_t)l * DD * FF, b2 + l * DD, q,
                              MM, DD, FF, 0);
        add_ln  <<<MM, 256>>>(x, q, ln2_g + l * DD, ln2_b + l * DD, x);
    }

    // final LN + LM head
    add_ln  <<<MM, 256>>>(x, (const float*)nullptr, lnf_g, lnf_b, x);
    sgemm_nt<<<gV, 256>>>(x, head_w, (const float*)nullptr, out, MM, VV, DD, 0);
}

// round 3
// speedup vs baseline: 1.9172x; 1.9172x over previous
#include <cuda_runtime.h>
#include <cuda_bf16.h>
#include <math.h>
#include <stdint.h>

// ---------------- problem constants ----------------------------------------
#define BB   2
#define SS   1024
#define DD   1024
#define HH   16
#define DKK  64
#define FF   4096
#define LL   4
#define VV   32000
#define MM   (BB*SS)
#define LNEPS 1e-5f

// ---------------- bf16 weight pool offsets (elements) ----------------------
#define SZ_D2   (LL*DD*DD)
#define SZ_FD   (LL*FF*DD)
#define SZ_HW   (VV*DD)
#define OFF_WQ  0
#define OFF_WK  (SZ_D2)
#define OFF_WV  (2*SZ_D2)
#define OFF_WO  (3*SZ_D2)
#define OFF_W1  (4*SZ_D2)
#define OFF_W2  (OFF_W1 + SZ_FD)
#define OFF_HW  (OFF_W2 + SZ_FD)
#define WTOT    (OFF_HW + SZ_HW)

// ---------------- device scratch (no allocation allowed) -------------------
__device__ float g_x [MM*DD];
__device__ float g_q [MM*DD];
__device__ float g_k [MM*DD];
__device__ float g_v [MM*DD];
__device__ float g_o [MM*DD];
__device__ float g_ff[MM*FF];
__device__ float g_sc[(size_t)BB*HH*SS*SS];
__device__ __nv_bfloat16 g_whi[WTOT];
__device__ __nv_bfloat16 g_wlo[WTOT];
__device__ __nv_bfloat16 g_ahi[MM*FF];
__device__ __nv_bfloat16 g_alo[MM*FF];

// ---------------- helpers ---------------------------------------------------
__device__ __forceinline__ uint32_t smem_u32(const void* p) {
    uint32_t a;
    asm("{ .reg .u64 t; cvta.to.shared.u64 t, %1; cvt.u32.u64 %0, t; }"
        : "=r"(a) : "l"(p));
    return a;
}

#define LDSM_X4(r0, r1, r2, r3, addr) \
    asm volatile("ldmatrix.sync.aligned.m8n8.x4.shared.b16 {%0,%1,%2,%3}, [%4];" \
                 : "=r"(r0), "=r"(r1), "=r"(r2), "=r"(r3) : "r"(addr))
#define LDSM_X2(r0, r1, addr) \
    asm volatile("ldmatrix.sync.aligned.m8n8.x2.shared.b16 {%0,%1}, [%2];" \
                 : "=r"(r0), "=r"(r1) : "r"(addr))
#define MMA_BF16(c0, c1, c2, c3, a0, a1, a2, a3, b0, b1) \
    asm volatile("mma.sync.aligned.m16n8k16.row.col.f32.bf16.bf16.f32 " \
                 "{%0,%1,%2,%3}, {%4,%5,%6,%7}, {%8,%9}, {%0,%1,%2,%3};" \
                 : "+f"(c0), "+f"(c1), "+f"(c2), "+f"(c3) \
                 : "r"(a0), "r"(a1), "r"(a2), "r"(a3), "r"(b0), "r"(b1))

// ---------------- split fp32 -> (hi, lo) bf16 -------------------------------
__global__ void split_bf16(const float* __restrict__ x,
                           __nv_bfloat16* __restrict__ hi,
                           __nv_bfloat16* __restrict__ lo, int n)
{
    int i = (blockIdx.x * 256 + threadIdx.x) * 4;
    if (i >= n) return;
    float4 v = *(const float4*)(x + i);
    __nv_bfloat16 h0 = __float2bfloat16(v.x);
    __nv_bfloat16 h1 = __float2bfloat16(v.y);
    __nv_bfloat16 h2 = __float2bfloat16(v.z);
    __nv_bfloat16 h3 = __float2bfloat16(v.w);
    hi[i + 0] = h0; hi[i + 1] = h1; hi[i + 2] = h2; hi[i + 3] = h3;
    lo[i + 0] = __float2bfloat16(v.x - __bfloat162float(h0));
    lo[i + 1] = __float2bfloat16(v.y - __bfloat162float(h1));
    lo[i + 2] = __float2bfloat16(v.z - __bfloat162float(h2));
    lo[i + 3] = __float2bfloat16(v.w - __bfloat162float(h3));
}

// ---------------- HMMA GEMM: C[M,N] = A[M,K] @ B[N,K]^T ---------------------
// 3-pass bf16 split accumulated in fp32 registers.
// CTA 128x128, 8 warps of 64x32, BK=32, double-buffered smem (stride 40 pad).
#define SASTRIDE 40

__global__ __launch_bounds__(256)
void gemm_mma(const __nv_bfloat16* __restrict__ Ahi, const __nv_bfloat16* __restrict__ Alo,
              const __nv_bfloat16* __restrict__ Bhi, const __nv_bfloat16* __restrict__ Blo,
              const float* __restrict__ bias, float* __restrict__ C,
              int M, int N, int K, int relu)
{
    __shared__ __nv_bfloat16 sA[2][128 * SASTRIDE];
    __shared__ __nv_bfloat16 sB[2][128 * SASTRIDE];

    int tid  = threadIdx.x;
    int lane = tid & 31;
    int wid  = tid >> 5;
    int wm   = (wid & 1) * 64;     // warp M offset within CTA tile
    int wn   = (wid >> 1) * 32;    // warp N offset
    int m0   = blockIdx.y * 128;
    int n0   = blockIdx.x * 128;

    float c[4][4][4];
#pragma unroll
    for (int i = 0; i < 4; i++)
#pragma unroll
        for (int j = 0; j < 4; j++)
#pragma unroll
            for (int r = 0; r < 4; r++) c[i][j][r] = 0.f;

    const int KC = K >> 5;     // 32-wide k chunks per pass
    const int T  = 3 * KC;     // hi*hi, hi*lo, lo*hi

    // per-thread staging slots
    int srow = tid >> 2, sseg = (tid & 3) * 8;        // first 256 rows worth
    int srow2 = (tid + 256) >> 2, sseg2 = ((tid + 256) & 3) * 8;

    uint4 ra0, ra1, rb0, rb1;

    // ---- fetch stage 0
    {
        const __nv_bfloat16* As = Ahi;
        const __nv_bfloat16* Bs = Bhi;
        ra0 = *(const uint4*)(As + (size_t)(m0 + srow)  * K + sseg);
        ra1 = *(const uint4*)(As + (size_t)(m0 + srow2) * K + sseg2);
        rb0 = *(const uint4*)(Bs + (size_t)(n0 + srow)  * K + sseg);
        rb1 = *(const uint4*)(Bs + (size_t)(n0 + srow2) * K + sseg2);
    }
    *(uint4*)&sA[0][srow  * SASTRIDE + sseg ] = ra0;
    *(uint4*)&sA[0][srow2 * SASTRIDE + sseg2] = ra1;
    *(uint4*)&sB[0][srow  * SASTRIDE + sseg ] = rb0;
    *(uint4*)&sB[0][srow2 * SASTRIDE + sseg2] = rb1;
    __syncthreads();

    for (int cc = 0; cc < T; ++cc) {
        int p = cc & 1;

        // fetch next stage into registers (overlaps with compute below)
        if (cc + 1 < T) {
            int nxt = cc + 1;
            int seg = nxt / KC;
            int k0  = (nxt - seg * KC) << 5;
            const __nv_bfloat16* As = (seg == 2) ? Alo : Ahi;
            const __nv_bfloat16* Bs = (seg == 1) ? Blo : Bhi;
            ra0 = *(const uint4*)(As + (size_t)(m0 + srow)  * K + k0 + sseg);
            ra1 = *(const uint4*)(As + (size_t)(m0 + srow2) * K + k0 + sseg2);
            rb0 = *(const uint4*)(Bs + (size_t)(n0 + srow)  * K + k0 + sseg);
            rb1 = *(const uint4*)(Bs + (size_t)(n0 + srow2) * K + k0 + sseg2);
        }

        // compute on buffer p
        uint32_t baseA = smem_u32(&sA[p][0]);
        uint32_t baseB = smem_u32(&sB[p][0]);
#pragma unroll
        for (int kk = 0; kk < 32; kk += 16) {
            uint32_t a[4][4], b[4][2];
#pragma unroll
            for (int ma = 0; ma < 4; ma++) {
                uint32_t addr = baseA +
                    (((wm + ma * 16 + (lane & 15)) * SASTRIDE) + kk + ((lane >> 4) * 8)) * 2;
                LDSM_X4(a[ma][0], a[ma][1], a[ma][2], a[ma][3], addr);
            }
#pragma unroll
            for (int nb = 0; nb < 4; nb++) {
                uint32_t addr = baseB +
                    (((wn + nb * 8 + (lane & 7)) * SASTRIDE) + kk + (((lane >> 3) & 1) * 8)) * 2;
                LDSM_X2(b[nb][0], b[nb][1], addr);
            }
#pragma unroll
            for (int ma = 0; ma < 4; ma++)
#pragma unroll
                for (int nb = 0; nb < 4; nb++)
                    MMA_BF16(c[ma][nb][0], c[ma][nb][1], c[ma][nb][2], c[ma][nb][3],
                             a[ma][0], a[ma][1], a[ma][2], a[ma][3],
                             b[nb][0], b[nb][1]);
        }

        // store next stage to the other buffer
        if (cc + 1 < T) {
            int q = p ^ 1;
            *(uint4*)&sA[q][srow  * SASTRIDE + sseg ] = ra0;
            *(uint4*)&sA[q][srow2 * SASTRIDE + sseg2] = ra1;
            *(uint4*)&sB[q][srow  * SASTRIDE + sseg ] = rb0;
            *(uint4*)&sB[q][srow2 * SASTRIDE + sseg2] = rb1;
        }
        __syncthreads();
    }

    // ---- epilogue
#pragma unroll
    for (int ma = 0; ma < 4; ma++) {
        int mrow = m0 + wm + ma * 16 + (lane >> 2);
#pragma unroll
        for (int nb = 0; nb < 4; nb++) {
            int ncol = n0 + wn + nb * 8 + (lane & 3) * 2;
            float b0 = 0.f, b1 = 0.f;
            if (bias) { b0 = bias[ncol]; b1 = bias[ncol + 1]; }
            float2 v0, v1;
            v0.x = c[ma][nb][0] + b0; v0.y = c[ma][nb][1] + b1;
            v1.x = c[ma][nb][2] + b0; v1.y = c[ma][nb][3] + b1;
            if (relu) {
                v0.x = fmaxf(v0.x, 0.f); v0.y = fmaxf(v0.y, 0.f);
                v1.x = fmaxf(v1.x, 0.f); v1.y = fmaxf(v1.y, 0.f);
            }
            *(float2*)(C + (size_t)mrow * N + ncol)       = v0;
            *(float2*)(C + (size_t)(mrow + 8) * N + ncol) = v1;
        }
    }
}

// ---------------- embedding + sinusoidal PE ---------------------------------
__global__ void embed_pe_kernel(const int* __restrict__ ids,
                                const float* __restrict__ emb,
                                float* __restrict__ x)
{
    int idx = blockIdx.x * 256 + threadIdx.x;
    int m = idx >> 10;
    int d = idx & 1023;
    int s = m & (SS - 1);
    int tok = ids[m];
    int twohalf = (d >> 1) << 1;
    float div = __expf(-(float)twohalf * (9.210340371976184f / (float)DD));
    float ang = (float)s * div;
    float pe  = (d & 1) ? cosf(ang) : sinf(ang);
    x[idx] = emb[(size_t)tok * DD + d] * 32.0f + pe;
}

// ---------------- attention scores (fp32 SIMT, causal) ----------------------
__global__ __launch_bounds__(256)
void attn_scores(const float* __restrict__ q, const float* __restrict__ kmat,
                 float* __restrict__ sc)
{
    int bh = blockIdx.z;
    int b = bh >> 4, h = bh & 15;
    int i0 = blockIdx.y * 128, j0 = blockIdx.x * 128;
    float* out = sc + (size_t)bh * SS * SS;
    int tid = threadIdx.x;

    if (j0 > i0 + 127) {
        for (int u = tid; u < 128 * 128; u += 256) {
            int i = u >> 7, j = u & 127;
            out[(size_t)(i0 + i) * SS + j0 + j] = -1e9f;
        }
        return;
    }
    const float* qb = q    + (size_t)b * SS * DD + h * DKK;
    const float* kb = kmat + (size_t)b * SS * DD + h * DKK;
    __shared__ float Qs[8][128];
    __shared__ float Ks[8][128];
    int lrow = tid >> 1, lcol = (tid & 1) << 2;
    int ty = tid >> 4, tx = tid & 15;
    float acc[8][8];
#pragma unroll
    for (int i = 0; i < 8; i++)
#pragma unroll
        for (int j = 0; j < 8; j++) acc[i][j] = 0.f;
    for (int k0 = 0; k0 < DKK; k0 += 8) {
        float4 av = *(const float4*)(qb + (size_t)(i0 + lrow) * DD + k0 + lcol);
        float4 bv = *(const float4*)(kb + (size_t)(j0 + lrow) * DD + k0 + lcol);
        __syncthreads();
        Qs[lcol + 0][lrow] = av.x; Qs[lcol + 1][lrow] = av.y;
        Qs[lcol + 2][lrow] = av.z; Qs[lcol + 3][lrow] = av.w;
        Ks[lcol + 0][lrow] = bv.x; Ks[lcol + 1][lrow] = bv.y;
        Ks[lcol + 2][lrow] = bv.z; Ks[lcol + 3][lrow] = bv.w;
        __syncthreads();
#pragma unroll
        for (int kk = 0; kk < 8; kk++) {
            float a[8], bb_[8];
#pragma unroll
            for (int i = 0; i < 8; i++) a[i]   = Qs[kk][ty * 8 + i];
#pragma unroll
            for (int j = 0; j < 8; j++) bb_[j] = Ks[kk][tx * 8 + j];
#pragma unroll
            for (int i = 0; i < 8; i++)
#pragma unroll
                for (int j = 0; j < 8; j++) acc[i][j] += a[i] * bb_[j];
        }
    }
    const float scale = 0.125f;
#pragma unroll
    for (int i = 0; i < 8; i++) {
        int row = i0 + ty * 8 + i;
#pragma unroll
        for (int j = 0; j < 8; j++) {
            int col = j0 + tx * 8 + j;
            float v = acc[i][j] * scale;
            if (col > row) v = -1e9f;
            out[(size_t)row * SS + col] = v;
        }
    }
}

// ---------------- row softmax ------------------------------------------------
__global__ __launch_bounds__(256)
void softmax_rows(float* __restrict__ sc)
{
    __shared__ float red[256];
    size_t row = blockIdx.x;
    float* p = sc + row * SS;
    int t = threadIdx.x;
    float v0 = p[t], v1 = p[t + 256], v2 = p[t + 512], v3 = p[t + 768];
    float m = fmaxf(fmaxf(v0, v1), fmaxf(v2, v3));
    red[t] = m; __syncthreads();
    for (int w = 128; w > 0; w >>= 1) {
        if (t < w) red[t] = fmaxf(red[t], red[t + w]);
        __syncthreads();
    }
    m = red[0]; __syncthreads();
    v0 = __expf(v0 - m); v1 = __expf(v1 - m);
    v2 = __expf(v2 - m); v3 = __expf(v3 - m);
    float s = v0 + v1 + v2 + v3;
    red[t] = s; __syncthreads();
    for (int w = 128; w > 0; w >>= 1) {
        if (t < w) red[t] += red[t + w];
        __syncthreads();
    }
    float inv = 1.f / red[0];
    p[t] = v0 * inv; p[t + 256] = v1 * inv;
    p[t + 512] = v2 * inv; p[t + 768] = v3 * inv;
}

// ---------------- o = attn @ v (causal K-truncated) --------------------------
__global__ __launch_bounds__(256)
void attn_av(const float* __restrict__ sc, const float* __restrict__ v,
             float* __restrict__ o)
{
    int bh = blockIdx.y;
    int b = bh >> 4, h = bh & 15;
    int i0 = blockIdx.x * 64;
    const float* A  = sc + (size_t)bh * SS * SS;
    const float* vb = v  + (size_t)b * SS * DD + h * DKK;
    __shared__ float As[16][64];
    __shared__ float Vs[16][64];
    int t  = threadIdx.x;
    int ar = t >> 2,  ac = (t & 3) << 2;
    int vr = t >> 4,  vc = (t & 15) << 2;
    int ty = t >> 4,  tx = t & 15;
    float acc[4][4];
#pragma unroll
    for (int i = 0; i < 4; i++)
#pragma unroll
        for (int j = 0; j < 4; j++) acc[i][j] = 0.f;
    int kmax = i0 + 64;
    for (int k0 = 0; k0 < kmax; k0 += 16) {
        float4 av = *(const float4*)(A  + (size_t)(i0 + ar) * SS + k0 + ac);
        float4 vv = *(const float4*)(vb + (size_t)(k0 + vr) * DD + vc);
        __syncthreads();
        As[ac + 0][ar] = av.x; As[ac + 1][ar] = av.y;
        As[ac + 2][ar] = av.z; As[ac + 3][ar] = av.w;
        *(float4*)&Vs[vr][vc] = vv;
        __syncthreads();
#pragma unroll
        for (int kk = 0; kk < 16; kk++) {
            float a[4], bv_[4];
#pragma unroll
            for (int i = 0; i < 4; i++) a[i]   = As[kk][ty * 4 + i];
#pragma unroll
            for (int j = 0; j < 4; j++) bv_[j] = Vs[kk][tx * 4 + j];
#pragma unroll
            for (int i = 0; i < 4; i++)
#pragma unroll
                for (int j = 0; j < 4; j++) acc[i][j] += a[i] * bv_[j];
        }
    }
#pragma unroll
    for (int i = 0; i < 4; i++)
#pragma unroll
        for (int j = 0; j < 4; j++)
            o[(size_t)(b * SS + i0 + ty * 4 + i) * DD + h * DKK + tx * 4 + j]
                = acc[i][j];
}

// ---------------- fused residual + LayerNorm --------------------------------
__global__ __launch_bounds__(256)
void add_ln(const float* __restrict__ x, const float* __restrict__ y,
            const float* __restrict__ g, const float* __restrict__ bta,
            float* __restrict__ out)
{
    __shared__ float red[256];
    int row = blockIdx.x;
    int t = threadIdx.x;
    const float* xr = x + (size_t)row * DD;
    float v[4];
    float s = 0.f;
#pragma unroll
    for (int u = 0; u < 4; u++) {
        int idx = t + u * 256;
        float vv = xr[idx];
        if (y) vv += y[(size_t)row * DD + idx];
        v[u] = vv;
        s += vv;
    }
    red[t] = s; __syncthreads();
    for (int w = 128; w > 0; w >>= 1) {
        if (t < w) red[t] += red[t + w];
        __syncthreads();
    }
    float mean = red[0] * (1.f / DD); __syncthreads();
    float s2 = 0.f;
#pragma unroll
    for (int u = 0; u < 4; u++) { float d = v[u] - mean; s2 += d * d; }
    red[t] = s2; __syncthreads();
    for (int w = 128; w > 0; w >>= 1) {
        if (t < w) red[t] += red[t + w];
        __syncthreads();
    }
    float rstd = rsqrtf(red[0] * (1.f / DD) + LNEPS);
    float* orow = out + (size_t)row * DD;
#pragma unroll
    for (int u = 0; u < 4; u++) {
        int idx = t + u * 256;
        orow[idx] = (v[u] - mean) * rstd * g[idx] + bta[idx];
    }
}

// ---------------- host orchestration ----------------------------------------
extern "C" void kernel_launch(void* const* d_in, const int* in_sizes, int n_in,
                              void* d_out, int out_size)
{
    (void)in_sizes; (void)n_in; (void)out_size;
    const int*   ids    = (const int*)  d_in[0];
    const float* embedw = (const float*)d_in[1];
    const float* Wq     = (const float*)d_in[2];
    const float* bq     = (const float*)d_in[3];
    const float* Wk     = (const float*)d_in[4];
    const float* bk     = (const float*)d_in[5];
    const float* Wv     = (const float*)d_in[6];
    const float* bv     = (const float*)d_in[7];
    const float* Wo     = (const float*)d_in[8];
    const float* bo     = (const float*)d_in[9];
    const float* ln1_g  = (const float*)d_in[10];
    const float* ln1_b  = (const float*)d_in[11];
    const float* W1     = (const float*)d_in[12];
    const float* b1     = (const float*)d_in[13];
    const float* W2     = (const float*)d_in[14];
    const float* b2     = (const float*)d_in[15];
    const float* ln2_g  = (const float*)d_in[16];
    const float* ln2_b  = (const float*)d_in[17];
    const float* lnf_g  = (const float*)d_in[18];
    const float* lnf_b  = (const float*)d_in[19];
    const float* head_w = (const float*)d_in[20];
    float* out = (float*)d_out;

    float *x, *q, *k, *v, *o, *ff, *sc;
    __nv_bfloat16 *whi, *wlo, *ahi, *alo;
    cudaGetSymbolAddress((void**)&x,  g_x);
    cudaGetSymbolAddress((void**)&q,  g_q);
    cudaGetSymbolAddress((void**)&k,  g_k);
    cudaGetSymbolAddress((void**)&v,  g_v);
    cudaGetSymbolAddress((void**)&o,  g_o);
    cudaGetSymbolAddress((void**)&ff, g_ff);
    cudaGetSymbolAddress((void**)&sc, g_sc);
    cudaGetSymbolAddress((void**)&whi, g_whi);
    cudaGetSymbolAddress((void**)&wlo, g_wlo);
    cudaGetSymbolAddress((void**)&ahi, g_ahi);
    cudaGetSymbolAddress((void**)&alo, g_alo);

    auto split = [&](const float* s, __nv_bfloat16* h, __nv_bfloat16* l, int n) {
        split_bf16<<<n / 1024, 256>>>(s, h, l, n);
    };
    auto gemm = [&](const __nv_bfloat16* aH, const __nv_bfloat16* aL,
                    const __nv_bfloat16* bH, const __nv_bfloat16* bL,
                    const float* bias, float* C, int M, int N, int K, int relu) {
        gemm_mma<<<dim3(N / 128, M / 128), 256>>>(aH, aL, bH, bL, bias, C,
                                                  M, N, K, relu);
    };

    // weight split (all layers at once)
    split(Wq,     whi + OFF_WQ, wlo + OFF_WQ, SZ_D2);
    split(Wk,     whi + OFF_WK, wlo + OFF_WK, SZ_D2);
    split(Wv,     whi + OFF_WV, wlo + OFF_WV, SZ_D2);
    split(Wo,     whi + OFF_WO, wlo + OFF_WO, SZ_D2);
    split(W1,     whi + OFF_W1, wlo + OFF_W1, SZ_FD);
    split(W2,     whi + OFF_W2, wlo + OFF_W2, SZ_FD);
    split(head_w, whi + OFF_HW, wlo + OFF_HW, SZ_HW);

    embed_pe_kernel<<<(MM * DD) / 256, 256>>>(ids, embedw, x);

    dim3 gSc(SS / 128, SS / 128, BB * HH);
    dim3 gAv(SS / 64, BB * HH);

    for (int l = 0; l < LL; l++) {
        size_t d2 = (size_t)l * DD * DD;
        size_t fd = (size_t)l * FF * DD;

        split(x, ahi, alo, MM * DD);
        gemm(ahi, alo, whi + OFF_WQ + d2, wlo + OFF_WQ + d2, bq + l * DD, q, MM, DD, DD, 0);
        gemm(ahi, alo, whi + OFF_WK + d2, wlo + OFF_WK + d2, bk + l * DD, k, MM, DD, DD, 0);
        gemm(ahi, alo, whi + OFF_WV + d2, wlo + OFF_WV + d2, bv + l * DD, v, MM, DD, DD, 0);

        attn_scores <<<gSc, 256>>>(q, k, sc);
        softmax_rows<<<BB * HH * SS, 256>>>(sc);
        attn_av     <<<gAv, 256>>>(sc, v, o);

        split(o, ahi, alo, MM * DD);
        gemm(ahi, alo, whi + OFF_WO + d2, wlo + OFF_WO + d2, bo + l * DD, q, MM, DD, DD, 0);
        add_ln<<<MM, 256>>>(x, q, ln1_g + l * DD, ln1_b + l * DD, x);

        split(x, ahi, alo, MM * DD);
        gemm(ahi, alo, whi + OFF_W1 + fd, wlo + OFF_W1 + fd, b1 + l * FF, ff, MM, FF, DD, 1);
        split(ff, ahi, alo, MM * FF);
        gemm(ahi, alo, whi + OFF_W2 + fd, wlo + OFF_W2 + fd, b2 + l * DD, q, MM, DD, FF, 0);
        add_ln<<<MM, 256>>>(x, q, ln2_g + l * DD, ln2_b + l * DD, x);
    }

    add_ln<<<MM, 256>>>(x, (const float*)nullptr, lnf_g, lnf_b, x);
    split(x, ahi, alo, MM * DD);
    gemm(ahi, alo, whi + OFF_HW, wlo + OFF_HW, (const float*)nullptr, out,
         MM, VV, DD, 0);
}